// round 11
// baseline (speedup 1.0000x reference)
#include <cuda_runtime.h>
#include <cuda_bf16.h>

// F0 via raw autocorrelation argmax (per-frame normalization is a positive
// scalar -> argmax invariant -> skipped).
// R2: frame-pairs packed in f32x2; all inner math fma.rn.f32x2.
// R7: ping-pong window banks A/B, 16-step unrolled chunks, chunk prefetch.
// R9: asymmetric lag-band warps per frame-pair:
//       warp A: lags  32..159 (4/lane), 480 steps
//       warp B: lags 160..255 (3/lane), 352 steps (products beyond are zero)
//     -11.4% issued FFMA2 (warp-uniform triangular trim), acc regs 14 -> 8/6,
//     expected ~5 blocks/SM without any launch_bounds reg cap (R8 spill lesson).

#define SR_I        16000
#define HOP         256
#define FRAME_LEN   512
#define MIN_PERIOD  32
#define PAIRS_PER_BLOCK 4      // 4 pairs * 2 warps = 8 warps = 256 threads
#define T_LEN       163840
#define N_FRAMES    641
#define BUF         740        // float2 slots; zero tail covers all window reads

#define FMA_F32X2(d, a, b, c) \
    asm("fma.rn.f32x2 %0, %1, %2, %3;" : "=l"(d) : "l"(a), "l"(b), "l"(c))

__device__ __forceinline__ unsigned long long pack2(float2 v) {
    unsigned long long r;
    asm("mov.b64 %0, {%1, %2};" : "=l"(r) : "f"(v.x), "f"(v.y));
    return r;
}
__device__ __forceinline__ float2 unpack2(unsigned long long v) {
    float2 r;
    asm("mov.b64 {%0, %1}, %2;" : "=f"(r.x), "=f"(r.y) : "l"(v));
    return r;
}

// Ping-pong chunked correlation loop. LPL lags/lane starting at 'base',
// NSTEPS multiple of 16. Window bank width 8 covers j+k <= 7+LPL-1 <= 13.
template <int LPL, int NSTEPS>
__device__ __forceinline__ void corr_loop(const float2* __restrict__ s2,
                                          const int base,
                                          unsigned long long (&acc)[LPL])
{
    unsigned long long A[8], B[8];
#pragma unroll
    for (int k = 0; k < 8; ++k) A[k] = pack2(s2[base + k]);

    int t = 0;
#pragma unroll 1
    for (int c = 0; c < NSTEPS / 16; ++c) {
        // half-chunk 1: window in A, prefetch B
#pragma unroll
        for (int k = 0; k < 8; ++k) B[k] = pack2(s2[t + base + 8 + k]);
#pragma unroll
        for (int j = 0; j < 8; ++j) {
            const unsigned long long sb = pack2(s2[t + j]);
#pragma unroll
            for (int k = 0; k < LPL; ++k) {
                const int idx = j + k;
                FMA_F32X2(acc[k], sb, (idx < 8) ? A[idx] : B[idx - 8], acc[k]);
            }
        }
        t += 8;
        // half-chunk 2: window in B, prefetch A
#pragma unroll
        for (int k = 0; k < 8; ++k) A[k] = pack2(s2[t + base + 8 + k]);
#pragma unroll
        for (int j = 0; j < 8; ++j) {
            const unsigned long long sb = pack2(s2[t + j]);
#pragma unroll
            for (int k = 0; k < LPL; ++k) {
                const int idx = j + k;
                FMA_F32X2(acc[k], sb, (idx < 8) ? B[idx] : A[idx - 8], acc[k]);
            }
        }
        t += 8;
    }
}

// Per-lane + warp argmax over LPL consecutive lags/lane; lowest lag wins ties.
template <int LPL>
__device__ __forceinline__ void band_argmax(const unsigned long long (&acc)[LPL],
                                            const int base,
                                            float& bvx, int& bpx,
                                            float& bvy, int& bpy)
{
    float2 a0 = unpack2(acc[0]);
    bvx = a0.x; bvy = a0.y; bpx = base; bpy = base;
#pragma unroll
    for (int k = 1; k < LPL; ++k) {
        float2 a = unpack2(acc[k]);
        if (a.x > bvx) { bvx = a.x; bpx = base + k; }
        if (a.y > bvy) { bvy = a.y; bpy = base + k; }
    }
#pragma unroll
    for (int off = 16; off > 0; off >>= 1) {
        const float ovx = __shfl_xor_sync(0xffffffffu, bvx, off);
        const int   opx = __shfl_xor_sync(0xffffffffu, bpx, off);
        const float ovy = __shfl_xor_sync(0xffffffffu, bvy, off);
        const int   opy = __shfl_xor_sync(0xffffffffu, bpy, off);
        if (ovx > bvx || (ovx == bvx && opx < bpx)) { bvx = ovx; bpx = opx; }
        if (ovy > bvy || (ovy == bvy && opy < bpy)) { bvy = ovy; bpy = opy; }
    }
}

__global__ __launch_bounds__(256) void f0_autocorr_r9_kernel(
    const float* __restrict__ x,   // (64, 1, 163840)
    float* __restrict__ out)       // (64, 641)
{
    __shared__ float2 sbuf[PAIRS_PER_BLOCK][BUF];          // 23.7 KB
    __shared__ float bv_sh[2][PAIRS_PER_BLOCK][2];
    __shared__ int   bp_sh[2][PAIRS_PER_BLOCK][2];

    const int b      = blockIdx.y;
    const int f_base = blockIdx.x * (2 * PAIRS_PER_BLOCK); // 8 frames/block
    const float* __restrict__ xb = x + (size_t)b * T_LEN;
    const int tid = threadIdx.x;

    // Fill: pair p holds frames (f_base+2p, f_base+2p+1) interleaved, then
    // zeros. xpad[j] = x[reflect(j-256)] (numpy 'reflect', pad = 256).
    for (int i = tid; i < PAIRS_PER_BLOCK * BUF; i += 256) {
        const int p = i / BUF;
        const int j = i - p * BUF;
        float2 v = make_float2(0.0f, 0.0f);
        if (j < FRAME_LEN) {
            const int fr = f_base + 2 * p;
            int g0 = fr * HOP + j - (FRAME_LEN / 2);
            int g1 = g0 + HOP;
            if (g0 < 0) g0 = -g0;
            if (g0 >= T_LEN) g0 = 2 * (T_LEN - 1) - g0;
            if (g1 >= T_LEN) g1 = 2 * (T_LEN - 1) - g1;
            v.x = xb[g0];
            v.y = xb[g1];
        }
        sbuf[p][j] = v;
    }
    __syncthreads();

    const int w    = tid >> 5;
    const int lane = tid & 31;
    const int pair = w >> 1;            // 0..3
    const int role = w & 1;             // 0 = low band, 1 = high band
    const float2* __restrict__ s2 = sbuf[pair];

    float bvx, bvy; int bpx, bpy;
    if (role == 0) {
        // lags 32..159, 4 per lane; lag 32 needs all 480 steps
        const int base = 32 + 4 * lane;
        unsigned long long acc[4] = {0ull, 0ull, 0ull, 0ull};
        corr_loop<4, 480>(s2, base, acc);
        band_argmax<4>(acc, base, bvx, bpx, bvy, bpy);
    } else {
        // lags 160..255, 3 per lane; all products zero for t >= 352
        const int base = 160 + 3 * lane;
        unsigned long long acc[3] = {0ull, 0ull, 0ull};
        corr_loop<3, 352>(s2, base, acc);
        band_argmax<3>(acc, base, bvx, bpx, bvy, bpy);
    }

    if (lane == 0) {
        bv_sh[role][pair][0] = bvx;  bp_sh[role][pair][0] = bpx;
        bv_sh[role][pair][1] = bvy;  bp_sh[role][pair][1] = bpy;
    }
    __syncthreads();

    // Combine bands: A's lags are strictly lower, so ties pick A
    // (matches jnp.argmax first-index semantics).
    if (tid < 2 * PAIRS_PER_BLOCK) {
        const int p  = tid >> 1;
        const int fi = tid & 1;
        const int fr = f_base + 2 * p + fi;
        if (fr < N_FRAMES) {
            float vA = bv_sh[0][p][fi]; int pA = bp_sh[0][p][fi];
            float vB = bv_sh[1][p][fi]; int pB = bp_sh[1][p][fi];
            const int   bp = (vB > vA) ? pB : pA;
            float r = (float)SR_I / ((float)bp + 1e-8f);
            out[(size_t)b * N_FRAMES + fr] = fminf(fmaxf(r, 50.0f), 500.0f);
        }
    }
}

extern "C" void kernel_launch(void* const* d_in, const int* in_sizes, int n_in,
                              void* d_out, int out_size)
{
    const float* x = (const float*)d_in[0];
    float* out = (float*)d_out;
    const int pairs = (N_FRAMES + 1) / 2;                       // 321
    dim3 grid((pairs + PAIRS_PER_BLOCK - 1) / PAIRS_PER_BLOCK,  // 81
              64);
    f0_autocorr_r9_kernel<<<grid, 256>>>(x, out);
}

// round 14
// speedup vs baseline: 1.8433x; 1.8433x over previous
#include <cuda_runtime.h>
#include <cuda_bf16.h>

// F0 via raw autocorrelation argmax (per-frame normalization is a positive
// scalar -> argmax invariant -> skipped).
// R2:  frame-pairs packed in f32x2; all inner math fma.rn.f32x2.
// R9:  asymmetric lag-band warps (occupancy 5 blocks/SM worked; strides broke).
// R11: conflict-free strides: band A = 5 lags/lane (stride 5 -> 16 distinct
//      banks/phase), band B = 2 lags/lane (2-way only, 20% of work). Triple
//      4-wide rotating window bank over a 12-step unrolled body: bank h
//      refilled after its last use in half-chunk h, consumed 8+ steps later.
//      Regs ~ 10 acc + 24 bank -> 5 blocks/SM without a launch_bounds cap.

#define SR_I        16000
#define HOP         256
#define FRAME_LEN   512
#define MIN_PERIOD  32
#define PAIRS_PER_BLOCK 4      // 4 pairs * 2 warps = 8 warps = 256 threads
#define T_LEN       163840
#define N_FRAMES    641
#define BUF         740        // float2 slots; zero tail covers all window reads

#define FMA_F32X2(d, a, b, c) \
    asm("fma.rn.f32x2 %0, %1, %2, %3;" : "=l"(d) : "l"(a), "l"(b), "l"(c))

__device__ __forceinline__ unsigned long long pack2(float2 v) {
    unsigned long long r;
    asm("mov.b64 %0, {%1, %2};" : "=l"(r) : "f"(v.x), "f"(v.y));
    return r;
}
__device__ __forceinline__ float2 unpack2(unsigned long long v) {
    float2 r;
    asm("mov.b64 {%0, %1}, %2;" : "=f"(r.x), "=f"(r.y) : "l"(v));
    return r;
}

// 12-step-unrolled correlation with a triple 4-wide rotating window bank.
// Window value w (relative to iteration start) lives in W[4*((w/4)%3) + w%4].
// Half-chunk h (steps 4h..4h+3) consumes banks; bank h is refilled with
// w = 12+4h..15+4h right AFTER its last use (end of half-chunk h) and is
// first consumed in half-chunk h+2 -> 8+ steps of LDS latency cover.
// Requires LPL <= 5 (max idx = 11 + LPL-1 <= 15). NITER*12 steps total.
template <int LPL, int NITER>
__device__ __forceinline__ void corr12(const float2* __restrict__ s2,
                                       const int base,
                                       unsigned long long (&acc)[LPL])
{
    unsigned long long W[12];
#pragma unroll
    for (int i = 0; i < 12; ++i) W[i] = pack2(s2[base + i]);

    int t = 0;
#pragma unroll 1
    for (int c = 0; c < NITER; ++c) {
#pragma unroll
        for (int h = 0; h < 3; ++h) {
#pragma unroll
            for (int jj = 0; jj < 4; ++jj) {
                const int j = 4 * h + jj;
                const unsigned long long sb = pack2(s2[t + j]);   // broadcast
#pragma unroll
                for (int k = 0; k < LPL; ++k) {
                    const int idx  = j + k;                        // 0..15
                    const int slot = 4 * ((idx >> 2) % 3) + (idx & 3);
                    FMA_F32X2(acc[k], sb, W[slot], acc[k]);
                }
            }
            // refill bank h with w = 12+4h .. 15+4h (stride-LPL across lanes)
#pragma unroll
            for (int i = 0; i < 4; ++i)
                W[4 * h + i] = pack2(s2[t + base + 12 + 4 * h + i]);
        }
        t += 12;
    }
}

// Per-lane + warp argmax over LPL consecutive lags/lane; lowest lag wins ties.
template <int LPL>
__device__ __forceinline__ void band_argmax(const unsigned long long (&acc)[LPL],
                                            const int base,
                                            float& bvx, int& bpx,
                                            float& bvy, int& bpy)
{
    float2 a0 = unpack2(acc[0]);
    bvx = a0.x; bvy = a0.y; bpx = base; bpy = base;
#pragma unroll
    for (int k = 1; k < LPL; ++k) {
        float2 a = unpack2(acc[k]);
        if (a.x > bvx) { bvx = a.x; bpx = base + k; }
        if (a.y > bvy) { bvy = a.y; bpy = base + k; }
    }
#pragma unroll
    for (int off = 16; off > 0; off >>= 1) {
        const float ovx = __shfl_xor_sync(0xffffffffu, bvx, off);
        const int   opx = __shfl_xor_sync(0xffffffffu, bpx, off);
        const float ovy = __shfl_xor_sync(0xffffffffu, bvy, off);
        const int   opy = __shfl_xor_sync(0xffffffffu, bpy, off);
        if (ovx > bvx || (ovx == bvx && opx < bpx)) { bvx = ovx; bpx = opx; }
        if (ovy > bvy || (ovy == bvy && opy < bpy)) { bvy = ovy; bpy = opy; }
    }
}

__global__ __launch_bounds__(256) void f0_autocorr_r11_kernel(
    const float* __restrict__ x,   // (64, 1, 163840)
    float* __restrict__ out)       // (64, 641)
{
    __shared__ float2 sbuf[PAIRS_PER_BLOCK][BUF];          // 23.7 KB
    __shared__ float bv_sh[2][PAIRS_PER_BLOCK][2];
    __shared__ int   bp_sh[2][PAIRS_PER_BLOCK][2];

    const int b      = blockIdx.y;
    const int f_base = blockIdx.x * (2 * PAIRS_PER_BLOCK); // 8 frames/block
    const float* __restrict__ xb = x + (size_t)b * T_LEN;
    const int tid = threadIdx.x;

    // Fill: pair p holds frames (f_base+2p, f_base+2p+1) interleaved, then
    // zeros. xpad[j] = x[reflect(j-256)] (numpy 'reflect', pad = 256).
    for (int i = tid; i < PAIRS_PER_BLOCK * BUF; i += 256) {
        const int p = i / BUF;
        const int j = i - p * BUF;
        float2 v = make_float2(0.0f, 0.0f);
        if (j < FRAME_LEN) {
            const int fr = f_base + 2 * p;
            int g0 = fr * HOP + j - (FRAME_LEN / 2);
            int g1 = g0 + HOP;
            if (g0 < 0) g0 = -g0;
            if (g0 >= T_LEN) g0 = 2 * (T_LEN - 1) - g0;
            if (g1 >= T_LEN) g1 = 2 * (T_LEN - 1) - g1;
            v.x = xb[g0];
            v.y = xb[g1];
        }
        sbuf[p][j] = v;
    }
    __syncthreads();

    const int w    = tid >> 5;
    const int lane = tid & 31;
    const int pair = w >> 1;            // 0..3
    const int role = w & 1;             // 0 = low band, 1 = high band
    const float2* __restrict__ s2 = sbuf[pair];

    float bvx, bvy; int bpx, bpy;
    if (role == 0) {
        // lags 32..191, 5 per lane (stride 5: conflict-free), 480 = 40*12 steps
        const int base = 32 + 5 * lane;
        unsigned long long acc[5] = {0ull, 0ull, 0ull, 0ull, 0ull};
        corr12<5, 40>(s2, base, acc);
        band_argmax<5>(acc, base, bvx, bpx, bvy, bpy);
    } else {
        // lags 192..255, 2 per lane; products zero for t >= 320 -> 324 = 27*12
        const int base = 192 + 2 * lane;
        unsigned long long acc[2] = {0ull, 0ull};
        corr12<2, 27>(s2, base, acc);
        band_argmax<2>(acc, base, bvx, bpx, bvy, bpy);
    }

    if (lane == 0) {
        bv_sh[role][pair][0] = bvx;  bp_sh[role][pair][0] = bpx;
        bv_sh[role][pair][1] = bvy;  bp_sh[role][pair][1] = bpy;
    }
    __syncthreads();

    // Combine bands: A's lags are strictly lower, so ties pick A
    // (matches jnp.argmax first-index semantics).
    if (tid < 2 * PAIRS_PER_BLOCK) {
        const int p  = tid >> 1;
        const int fi = tid & 1;
        const int fr = f_base + 2 * p + fi;
        if (fr < N_FRAMES) {
            float vA = bv_sh[0][p][fi]; int pA = bp_sh[0][p][fi];
            float vB = bv_sh[1][p][fi]; int pB = bp_sh[1][p][fi];
            const int bp = (vB > vA) ? pB : pA;
            float r = (float)SR_I / ((float)bp + 1e-8f);
            out[(size_t)b * N_FRAMES + fr] = fminf(fmaxf(r, 50.0f), 500.0f);
        }
    }
}

extern "C" void kernel_launch(void* const* d_in, const int* in_sizes, int n_in,
                              void* d_out, int out_size)
{
    const float* x = (const float*)d_in[0];
    float* out = (float*)d_out;
    const int pairs = (N_FRAMES + 1) / 2;                       // 321
    dim3 grid((pairs + PAIRS_PER_BLOCK - 1) / PAIRS_PER_BLOCK,  // 81
              64);
    f0_autocorr_r11_kernel<<<grid, 256>>>(x, out);
}